// round 2
// baseline (speedup 1.0000x reference)
#include <cuda_runtime.h>
#include <cstdint>
#include <cstdio>

// ---------------------------------------------------------------------------
// VQ-VAE forward pass, sm_100a. Direct convolutions (round 1 baseline).
// Shapes are fixed by the problem:
//   inputs (16,3,256,256)
//   enc1: 3->64  k4 s2 p1 -> (16,64,128,128)
//   enc2: 64->128 k4 s2 p1 -> (16,128,64,64)
//   enc3: 128->128 k3 s1 p1
//   3x resblock(128): [3x3 128->64 relu, 1x1 64->128 relu, add]
//   vq conv: 128->64 1x1 -> z (16,64,64,64)
//   VQ vs codebook (512,64); q_st == q numerically; commitment = 1.25*mse(q,z)
//   dec1: 64->64 k3 p1
//   3x resblock(64): [3x3 64->32 relu, 1x1 32->64 relu, add]
//   deconv1: 64->32 k4 s2 p1 -> (16,32,128,128)
//   deconv2: 32->3  k4 s2 p1 -> (16,3,256,256) = rec
//   out = [rec (3145728 floats), total_loss, reconstruction_loss]
// ---------------------------------------------------------------------------

#define NB 16

// Scratch buffers (device globals: allocation-free per harness rules)
__device__ float g_bufA[(size_t)NB * 64 * 128 * 128];  // enc1 out
__device__ float g_bufB[(size_t)NB * 128 * 64 * 64];   // ping
__device__ float g_bufC[(size_t)NB * 128 * 64 * 64];   // pong
__device__ float g_half[(size_t)NB * 64 * 64 * 64];    // resblock hidden
__device__ float g_z[(size_t)NB * 64 * 64 * 64];
__device__ float g_q[(size_t)NB * 64 * 64 * 64];
__device__ float g_d1[(size_t)NB * 64 * 64 * 64];
__device__ float g_d2[(size_t)NB * 64 * 64 * 64];
__device__ float g_e[(size_t)NB * 32 * 128 * 128];     // deconv1 out
__device__ double g_vq_loss;
__device__ double g_rec_loss;

__global__ void zero_losses_kernel() {
    g_vq_loss = 0.0;
    g_rec_loss = 0.0;
}

// ---------------------------------------------------------------------------
// Generic direct conv. One thread per output element.
// grid = (spatialBlocks, Co, N). Weights for this co staged in shared memory.
// w layout: (Co, Ci, K, K). residual (nullable) added AFTER relu.
// ---------------------------------------------------------------------------
template <int K, int S, int P, bool RELU>
__global__ void __launch_bounds__(256) conv2d_k(
    const float* __restrict__ in, const float* __restrict__ w,
    const float* __restrict__ bias, const float* __restrict__ residual,
    float* __restrict__ out,
    int Ci, int Hi, int Wi, int Co, int Ho, int Wo)
{
    __shared__ float sw[1280];  // max Ci*K*K = 128*9 = 1152
    const int n = blockIdx.z;
    const int co = blockIdx.y;
    const int wsz = Ci * K * K;
    for (int i = threadIdx.x; i < wsz; i += blockDim.x)
        sw[i] = w[(size_t)co * wsz + i];
    __syncthreads();

    const int sp = blockIdx.x * blockDim.x + threadIdx.x;
    if (sp >= Ho * Wo) return;
    const int oh = sp / Wo;
    const int ow = sp - oh * Wo;

    float acc = bias ? bias[co] : 0.0f;
    const float* inb = in + (size_t)n * Ci * Hi * Wi;

    for (int ci = 0; ci < Ci; ci++) {
        const float* ip = inb + (size_t)ci * Hi * Wi;
        const float* wp = sw + ci * K * K;
        #pragma unroll
        for (int kh = 0; kh < K; kh++) {
            const int ih = oh * S - P + kh;
            if (ih < 0 || ih >= Hi) continue;
            const float* irow = ip + (size_t)ih * Wi;
            #pragma unroll
            for (int kw = 0; kw < K; kw++) {
                const int iw = ow * S - P + kw;
                if (iw < 0 || iw >= Wi) continue;
                acc = fmaf(irow[iw], wp[kh * K + kw], acc);
            }
        }
    }
    if (RELU) acc = fmaxf(acc, 0.0f);
    const size_t oidx = (((size_t)n * Co + co) * Ho + oh) * Wo + ow;
    if (residual) acc += residual[oidx];
    out[oidx] = acc;
}

// ---------------------------------------------------------------------------
// Transposed conv, k=4, s=2, p=1. w layout: (Ci, Co, 4, 4).
// out[n,co,oh,ow] = b[co] + sum_{ci,kh,kw : (oh+1-kh) even, ih in range}
//                   in[n,ci,ih,iw] * w[ci,co,kh,kw],  ih = (oh+1-kh)/2
// ---------------------------------------------------------------------------
__global__ void __launch_bounds__(256) deconv_k4s2(
    const float* __restrict__ in, const float* __restrict__ w,
    const float* __restrict__ bias, float* __restrict__ out,
    int Ci, int Hi, int Wi, int Co, int Ho, int Wo)
{
    __shared__ float sw[1024];  // Ci*16, max 64*16
    const int n = blockIdx.z;
    const int co = blockIdx.y;
    for (int i = threadIdx.x; i < Ci * 16; i += blockDim.x) {
        const int ci = i >> 4;
        const int t = i & 15;
        sw[i] = w[((size_t)ci * Co + co) * 16 + t];
    }
    __syncthreads();

    const int sp = blockIdx.x * blockDim.x + threadIdx.x;
    if (sp >= Ho * Wo) return;
    const int oh = sp / Wo;
    const int ow = sp - oh * Wo;

    float acc = bias[co];
    const float* inb = in + (size_t)n * Ci * Hi * Wi;

    for (int ci = 0; ci < Ci; ci++) {
        const float* ip = inb + (size_t)ci * Hi * Wi;
        const float* wp = sw + ci * 16;
        #pragma unroll
        for (int kh = 0; kh < 4; kh++) {
            const int ih2 = oh + 1 - kh;
            if (ih2 & 1) continue;
            const int ih = ih2 >> 1;
            if (ih < 0 || ih >= Hi) continue;
            const float* irow = ip + (size_t)ih * Wi;
            #pragma unroll
            for (int kw = 0; kw < 4; kw++) {
                const int iw2 = ow + 1 - kw;
                if (iw2 & 1) continue;
                const int iw = iw2 >> 1;
                if (iw < 0 || iw >= Wi) continue;
                acc = fmaf(irow[iw], wp[kh * 4 + kw], acc);
            }
        }
    }
    out[(((size_t)n * Co + co) * Ho + oh) * Wo + ow] = acc;
}

// ---------------------------------------------------------------------------
// Block-wide sum reduction
// ---------------------------------------------------------------------------
__device__ __forceinline__ float blockReduceSum(float v) {
    __shared__ float sh[32];
    #pragma unroll
    for (int o = 16; o > 0; o >>= 1) v += __shfl_down_sync(0xffffffffu, v, o);
    if ((threadIdx.x & 31) == 0) sh[threadIdx.x >> 5] = v;
    __syncthreads();
    const int nw = (blockDim.x + 31) >> 5;
    v = (threadIdx.x < (unsigned)nw) ? sh[threadIdx.x] : 0.0f;
    if (threadIdx.x < 32) {
        #pragma unroll
        for (int o = 16; o > 0; o >>= 1) v += __shfl_down_sync(0xffffffffu, v, o);
    }
    return v;
}

// ---------------------------------------------------------------------------
// Vector quantization. One thread per spatial position (65536 total).
// Full codebook (512x64 f32 = 128KB) + norms staged in dynamic shared memory.
// dist = ||z||^2 - 2 z.c + ||c||^2 (same expansion as the reference argmin).
// Writes q (NCHW) and accumulates exact sum((z-q)^2) into g_vq_loss.
// ---------------------------------------------------------------------------
#define VQ_K 512
#define VQ_D 64
#define VQ_SMEM ((VQ_K * VQ_D + VQ_K) * 4)

__global__ void __launch_bounds__(128) vq_kernel(
    const float* __restrict__ z, const float* __restrict__ cb,
    float* __restrict__ q)
{
    extern __shared__ float smem[];
    float* scb = smem;               // 512*64
    float* snorm = smem + VQ_K * VQ_D;  // 512

    for (int i = threadIdx.x; i < VQ_K * VQ_D; i += blockDim.x)
        scb[i] = cb[i];
    __syncthreads();
    for (int c = threadIdx.x; c < VQ_K; c += blockDim.x) {
        float s = 0.0f;
        const float* cp = scb + c * VQ_D;
        #pragma unroll 16
        for (int d = 0; d < VQ_D; d++) s = fmaf(cp[d], cp[d], s);
        snorm[c] = s;
    }
    __syncthreads();

    const int pos = blockIdx.x * blockDim.x + threadIdx.x;  // < 65536
    const int n = pos >> 12;        // / 4096
    const int hw = pos & 4095;

    float zv[VQ_D];
    const float* zp = z + (size_t)n * VQ_D * 4096 + hw;
    float zn = 0.0f;
    #pragma unroll
    for (int d = 0; d < VQ_D; d++) {
        zv[d] = zp[(size_t)d * 4096];
        zn = fmaf(zv[d], zv[d], zn);
    }

    float bestd = 3.402823466e+38f;
    int besti = 0;
    for (int c = 0; c < VQ_K; c++) {
        const float4* cp4 = reinterpret_cast<const float4*>(scb + c * VQ_D);
        float dot = 0.0f;
        #pragma unroll
        for (int d4 = 0; d4 < VQ_D / 4; d4++) {
            const float4 cv = cp4[d4];
            dot = fmaf(zv[4 * d4 + 0], cv.x, dot);
            dot = fmaf(zv[4 * d4 + 1], cv.y, dot);
            dot = fmaf(zv[4 * d4 + 2], cv.z, dot);
            dot = fmaf(zv[4 * d4 + 3], cv.w, dot);
        }
        const float dist = zn - 2.0f * dot + snorm[c];
        if (dist < bestd) { bestd = dist; besti = c; }
    }

    // Write q and accumulate exact (z-q)^2
    float lsum = 0.0f;
    const float* cp = scb + besti * VQ_D;
    float* qp = q + (size_t)n * VQ_D * 4096 + hw;
    #pragma unroll
    for (int d = 0; d < VQ_D; d++) {
        const float cv = cp[d];
        qp[(size_t)d * 4096] = cv;
        const float df = zv[d] - cv;
        lsum = fmaf(df, df, lsum);
    }
    const float bsum = blockReduceSum(lsum);
    if (threadIdx.x == 0) atomicAdd(&g_vq_loss, (double)bsum);
}

// ---------------------------------------------------------------------------
// Reconstruction loss: sum (rec - inputs)^2
// ---------------------------------------------------------------------------
__global__ void __launch_bounds__(256) recon_loss_kernel(
    const float* __restrict__ rec, const float* __restrict__ inp, int total)
{
    float lsum = 0.0f;
    for (int i = blockIdx.x * blockDim.x + threadIdx.x; i < total;
         i += gridDim.x * blockDim.x) {
        const float d = rec[i] - inp[i];
        lsum = fmaf(d, d, lsum);
    }
    const float bsum = blockReduceSum(lsum);
    if (threadIdx.x == 0) atomicAdd(&g_rec_loss, (double)bsum);
}

__global__ void finalize_kernel(float* out, int out_size) {
    const double recon = g_rec_loss / 3145728.0;          // 16*3*256*256
    const double vq = g_vq_loss / 4194304.0;              // 16*64*64*64
    out[out_size - 2] = (float)(recon + 1.25 * vq);       // total_loss
    out[out_size - 1] = (float)recon;                     // reconstruction_loss
}

// ---------------------------------------------------------------------------
extern "C" void kernel_launch(void* const* d_in, const int* in_sizes, int n_in,
                              void* d_out, int out_size)
{
    const float* inp       = (const float*)d_in[0];
    const float* enc_w1    = (const float*)d_in[1];
    const float* enc_b1    = (const float*)d_in[2];
    const float* enc_w2    = (const float*)d_in[3];
    const float* enc_b2    = (const float*)d_in[4];
    const float* enc_w3    = (const float*)d_in[5];
    const float* enc_b3    = (const float*)d_in[6];
    const float* enc_res_w1 = (const float*)d_in[7];   // (3,64,128,3,3)
    const float* enc_res_w2 = (const float*)d_in[8];   // (3,128,64,1,1)
    const float* vq_w      = (const float*)d_in[9];
    const float* vq_b      = (const float*)d_in[10];
    const float* codebook  = (const float*)d_in[11];
    const float* dec_w1    = (const float*)d_in[12];
    const float* dec_b1    = (const float*)d_in[13];
    const float* dec_res_w1 = (const float*)d_in[14];  // (3,32,64,3,3)
    const float* dec_res_w2 = (const float*)d_in[15];  // (3,64,32,1,1)
    const float* dec_w2t   = (const float*)d_in[16];   // (64,32,4,4)
    const float* dec_b2    = (const float*)d_in[17];
    const float* dec_w3t   = (const float*)d_in[18];   // (32,3,4,4)
    const float* dec_b3    = (const float*)d_in[19];

    float *bufA, *bufB, *bufC, *half, *zb, *qb, *d1, *d2, *eb;
    cudaGetSymbolAddress((void**)&bufA, g_bufA);
    cudaGetSymbolAddress((void**)&bufB, g_bufB);
    cudaGetSymbolAddress((void**)&bufC, g_bufC);
    cudaGetSymbolAddress((void**)&half, g_half);
    cudaGetSymbolAddress((void**)&zb, g_z);
    cudaGetSymbolAddress((void**)&qb, g_q);
    cudaGetSymbolAddress((void**)&d1, g_d1);
    cudaGetSymbolAddress((void**)&d2, g_d2);
    cudaGetSymbolAddress((void**)&eb, g_e);

    cudaFuncSetAttribute(vq_kernel, cudaFuncAttributeMaxDynamicSharedMemorySize,
                         VQ_SMEM);

    zero_losses_kernel<<<1, 1>>>();

    // Encoder
    conv2d_k<4, 2, 1, false><<<dim3(64, 64, NB), 256>>>(
        inp, enc_w1, enc_b1, nullptr, bufA, 3, 256, 256, 64, 128, 128);
    conv2d_k<4, 2, 1, false><<<dim3(16, 128, NB), 256>>>(
        bufA, enc_w2, enc_b2, nullptr, bufB, 64, 128, 128, 128, 64, 64);
    conv2d_k<3, 1, 1, false><<<dim3(16, 128, NB), 256>>>(
        bufB, enc_w3, enc_b3, nullptr, bufC, 128, 64, 64, 128, 64, 64);

    // Encoder resblocks (128ch): ping-pong bufC <-> bufB
    {
        float* cur = bufC;
        float* alt = bufB;
        for (int i = 0; i < 3; i++) {
            conv2d_k<3, 1, 1, true><<<dim3(16, 64, NB), 256>>>(
                cur, enc_res_w1 + (size_t)i * 64 * 128 * 9, nullptr, nullptr,
                half, 128, 64, 64, 64, 64, 64);
            conv2d_k<1, 1, 0, true><<<dim3(16, 128, NB), 256>>>(
                half, enc_res_w2 + (size_t)i * 128 * 64, nullptr, cur,
                alt, 64, 64, 64, 128, 64, 64);
            float* t = cur; cur = alt; alt = t;
        }
        // cur now holds the pre-VQ features
        conv2d_k<1, 1, 0, false><<<dim3(16, 64, NB), 256>>>(
            cur, vq_w, vq_b, nullptr, zb, 128, 64, 64, 64, 64, 64);
    }

    // Vector quantization (q_st == q numerically)
    vq_kernel<<<512, 128, VQ_SMEM>>>(zb, codebook, qb);

    // Decoder
    conv2d_k<3, 1, 1, false><<<dim3(16, 64, NB), 256>>>(
        qb, dec_w1, dec_b1, nullptr, d1, 64, 64, 64, 64, 64, 64);
    {
        float* cur = d1;
        float* alt = d2;
        for (int i = 0; i < 3; i++) {
            conv2d_k<3, 1, 1, true><<<dim3(16, 32, NB), 256>>>(
                cur, dec_res_w1 + (size_t)i * 32 * 64 * 9, nullptr, nullptr,
                half, 64, 64, 64, 32, 64, 64);
            conv2d_k<1, 1, 0, true><<<dim3(16, 64, NB), 256>>>(
                half, dec_res_w2 + (size_t)i * 64 * 32, nullptr, cur,
                alt, 32, 64, 64, 64, 64, 64);
            float* t = cur; cur = alt; alt = t;
        }
        deconv_k4s2<<<dim3(64, 32, NB), 256>>>(
            cur, dec_w2t, dec_b2, eb, 64, 64, 64, 32, 128, 128);
    }
    deconv_k4s2<<<dim3(256, 3, NB), 256>>>(
        eb, dec_w3t, dec_b3, (float*)d_out, 32, 128, 128, 3, 256, 256);

    // Losses
    recon_loss_kernel<<<1024, 256>>>((const float*)d_out, inp, 3145728);
    finalize_kernel<<<1, 1>>>((float*)d_out, out_size);
}

// round 3
// speedup vs baseline: 3.2365x; 3.2365x over previous
#include <cuda_runtime.h>
#include <cstdint>

// ---------------------------------------------------------------------------
// VQ-VAE forward, sm_100a. Round 2: register/smem-tiled direct convolutions.
//   enc1: 3->64  k4 s2 p1  (256->128)      [conv4x4s2_tiled]
//   enc2: 64->128 k4 s2 p1 (128->64)       [conv4x4s2_tiled]
//   enc3: 128->128 k3 p1                   [conv3x3_tiled]
//   3x enc-res: 3x3 128->64 relu, 1x1 64->128 relu + add
//   vq conv 128->64 1x1 bias
//   VQ (512x64 codebook), q_st == q numerically
//   dec1: 64->64 k3 p1
//   3x dec-res: 3x3 64->32 relu, 1x1 32->64 relu + add
//   deconv1: 64->32 k4 s2 p1 (64->128)     [deconv4x4s2_tiled]
//   deconv2: 32->3  k4 s2 p1 (128->256) -> rec
//   out = [rec, total_loss, reconstruction_loss]
// ---------------------------------------------------------------------------

#define NB 16

__device__ float g_bufA[(size_t)NB * 64 * 128 * 128];
__device__ float g_bufB[(size_t)NB * 128 * 64 * 64];
__device__ float g_bufC[(size_t)NB * 128 * 64 * 64];
__device__ float g_half[(size_t)NB * 64 * 64 * 64];
__device__ float g_z[(size_t)NB * 64 * 64 * 64];
__device__ float g_q[(size_t)NB * 64 * 64 * 64];
__device__ float g_d1[(size_t)NB * 64 * 64 * 64];
__device__ float g_d2[(size_t)NB * 64 * 64 * 64];
__device__ float g_e[(size_t)NB * 32 * 128 * 128];
__device__ double g_vq_loss;
__device__ double g_rec_loss;

__global__ void zero_losses_kernel() {
    g_vq_loss = 0.0;
    g_rec_loss = 0.0;
}

// ---------------------------------------------------------------------------
// 3x3 conv, stride 1, pad 1, H=W=64. Block: 256 threads (16x16).
// Block tile: 32x32 outputs x 8 co. Thread: 2x2 outputs x 8 co (32 accs).
// grid = (4, Co/8, N)
// ---------------------------------------------------------------------------
template <bool RELU, bool BIAS>
__global__ void __launch_bounds__(256) conv3x3_tiled(
    const float* __restrict__ in, const float* __restrict__ w,
    const float* __restrict__ bias, float* __restrict__ out,
    int Ci, int Co)
{
    __shared__ float sIn[8][34][35];   // odd row stride: conflict-free
    __shared__ float sW[8][8][9];

    const int n = blockIdx.z;
    const int cog = blockIdx.y;
    const int oh0 = (blockIdx.x >> 1) * 32;
    const int ow0 = (blockIdx.x & 1) * 32;
    const int t = threadIdx.x;
    const int tx = t & 15, ty = t >> 4;

    float acc[8][4];
    #pragma unroll
    for (int i = 0; i < 8; i++)
        #pragma unroll
        for (int j = 0; j < 4; j++) acc[i][j] = 0.0f;

    const float* inb = in + (size_t)n * Ci * 4096;

    for (int cb = 0; cb < Ci; cb += 8) {
        __syncthreads();
        // stage input chunk: 8 ci x 34x34 (with halo, zero-padded)
        for (int i = t; i < 8 * 34 * 34; i += 256) {
            const int ci = i / 1156;
            const int rem = i - ci * 1156;
            const int r = rem / 34;
            const int c = rem - r * 34;
            const int ih = oh0 - 1 + r;
            const int iw = ow0 - 1 + c;
            float v = 0.0f;
            if (ih >= 0 && ih < 64 && iw >= 0 && iw < 64)
                v = inb[(size_t)(cb + ci) * 4096 + ih * 64 + iw];
            sIn[ci][r][c] = v;
        }
        // stage weights: 8 co x 8 ci x 9
        for (int i = t; i < 8 * 8 * 9; i += 256) {
            const int co = i / 72;
            const int rem = i - co * 72;
            const int ci = rem / 9;
            const int k = rem - ci * 9;
            sW[co][ci][k] = w[(((size_t)(cog * 8 + co)) * Ci + cb + ci) * 9 + k];
        }
        __syncthreads();

        #pragma unroll 1
        for (int ci = 0; ci < 8; ci++) {
            float iv[4][4];
            #pragma unroll
            for (int r = 0; r < 4; r++)
                #pragma unroll
                for (int c = 0; c < 4; c++)
                    iv[r][c] = sIn[ci][2 * ty + r][2 * tx + c];
            #pragma unroll
            for (int co = 0; co < 8; co++) {
                #pragma unroll
                for (int r2 = 0; r2 < 2; r2++)
                    #pragma unroll
                    for (int c2 = 0; c2 < 2; c2++) {
                        float a = acc[co][r2 * 2 + c2];
                        #pragma unroll
                        for (int kh = 0; kh < 3; kh++)
                            #pragma unroll
                            for (int kw = 0; kw < 3; kw++)
                                a = fmaf(iv[r2 + kh][c2 + kw],
                                         sW[co][ci][kh * 3 + kw], a);
                        acc[co][r2 * 2 + c2] = a;
                    }
            }
        }
    }

    float* outb = out + ((size_t)n * Co + cog * 8) * 4096;
    #pragma unroll
    for (int co = 0; co < 8; co++) {
        const float b = BIAS ? bias[cog * 8 + co] : 0.0f;
        #pragma unroll
        for (int r2 = 0; r2 < 2; r2++) {
            const int oh = oh0 + 2 * ty + r2;
            float v0 = acc[co][r2 * 2 + 0] + b;
            float v1 = acc[co][r2 * 2 + 1] + b;
            if (RELU) { v0 = fmaxf(v0, 0.0f); v1 = fmaxf(v1, 0.0f); }
            float2 p = make_float2(v0, v1);
            *reinterpret_cast<float2*>(
                outb + (size_t)co * 4096 + oh * 64 + ow0 + 2 * tx) = p;
        }
    }
}

// ---------------------------------------------------------------------------
// 4x4 conv, stride 2, pad 1 (enc1, enc2). Block: 256 threads (16x16).
// Block tile: 32x32 outputs x 8 co. Thread: 2x2 outputs x 8 co.
// Dynamic smem: sIn[4][66][67] + sW[8][4][16].
// grid = ((Ho/32)*(Wo/32), Co/8, N)
// ---------------------------------------------------------------------------
#define K4_SMEM ((4 * 66 * 67 + 8 * 4 * 16) * 4)

__global__ void __launch_bounds__(256) conv4x4s2_tiled(
    const float* __restrict__ in, const float* __restrict__ w,
    const float* __restrict__ bias, float* __restrict__ out,
    int Ci, int Hi, int Wi, int Co, int Ho, int Wo)
{
    extern __shared__ float sm[];
    float (*sIn)[66][67] = reinterpret_cast<float(*)[66][67]>(sm);
    float* sWp = sm + 4 * 66 * 67;

    const int n = blockIdx.z;
    const int cog = blockIdx.y;
    const int ntx = Wo >> 5;
    const int tileY = blockIdx.x / ntx;
    const int tileX = blockIdx.x - tileY * ntx;
    const int oh0 = tileY * 32, ow0 = tileX * 32;
    const int t = threadIdx.x;
    const int tx = t & 15, ty = t >> 4;

    float acc[8][4];
    #pragma unroll
    for (int i = 0; i < 8; i++)
        #pragma unroll
        for (int j = 0; j < 4; j++) acc[i][j] = 0.0f;

    const float* inb = in + (size_t)n * Ci * Hi * Wi;

    for (int cb = 0; cb < Ci; cb += 4) {
        __syncthreads();
        for (int i = t; i < 4 * 66 * 66; i += 256) {
            const int ci = i / 4356;
            const int rem = i - ci * 4356;
            const int r = rem / 66;
            const int c = rem - r * 66;
            const int ih = oh0 * 2 - 1 + r;
            const int iw = ow0 * 2 - 1 + c;
            const int cig = cb + ci;
            float v = 0.0f;
            if (cig < Ci && ih >= 0 && ih < Hi && iw >= 0 && iw < Wi)
                v = inb[(size_t)cig * Hi * Wi + ih * Wi + iw];
            sIn[ci][r][c] = v;
        }
        for (int i = t; i < 8 * 4 * 16; i += 256) {
            const int co = i >> 6;
            const int rem = i & 63;
            const int ci = rem >> 4;
            const int k = rem & 15;
            const int cig = cb + ci;
            sWp[i] = (cig < Ci)
                ? w[(((size_t)(cog * 8 + co)) * Ci + cig) * 16 + k] : 0.0f;
        }
        __syncthreads();

        #pragma unroll 1
        for (int ci = 0; ci < 4; ci++) {
            float iv[6][6];
            #pragma unroll
            for (int r = 0; r < 6; r++)
                #pragma unroll
                for (int c = 0; c < 6; c++)
                    iv[r][c] = sIn[ci][4 * ty + r][4 * tx + c];
            #pragma unroll
            for (int co = 0; co < 8; co++) {
                const float* wp = sWp + (co * 4 + ci) * 16;
                #pragma unroll
                for (int r2 = 0; r2 < 2; r2++)
                    #pragma unroll
                    for (int c2 = 0; c2 < 2; c2++) {
                        float a = acc[co][r2 * 2 + c2];
                        #pragma unroll
                        for (int kh = 0; kh < 4; kh++)
                            #pragma unroll
                            for (int kw = 0; kw < 4; kw++)
                                a = fmaf(iv[2 * r2 + kh][2 * c2 + kw],
                                         wp[kh * 4 + kw], a);
                        acc[co][r2 * 2 + c2] = a;
                    }
            }
        }
    }

    #pragma unroll
    for (int co = 0; co < 8; co++) {
        const float b = bias[cog * 8 + co];
        float* ob = out + ((size_t)n * Co + cog * 8 + co) * Ho * Wo;
        #pragma unroll
        for (int r2 = 0; r2 < 2; r2++) {
            const int oh = oh0 + 2 * ty + r2;
            float2 p = make_float2(acc[co][r2 * 2 + 0] + b,
                                   acc[co][r2 * 2 + 1] + b);
            *reinterpret_cast<float2*>(ob + (size_t)oh * Wo + ow0 + 2 * tx) = p;
        }
    }
}

// ---------------------------------------------------------------------------
// 1x1 conv = GEMM over 4096 spatial. Block 256 threads; thread: 4 hw x 8 co.
// grid = (4, Co/8, N). Weights (8 x Ci) staged in smem; float4 input stream.
// ---------------------------------------------------------------------------
template <bool RELU, bool BIAS, bool RES>
__global__ void __launch_bounds__(256) conv1x1_k(
    const float* __restrict__ in, const float* __restrict__ w,
    const float* __restrict__ bias, const float* __restrict__ res,
    float* __restrict__ out, int Ci, int Co)
{
    __shared__ float sW1[8 * 128];
    const int n = blockIdx.z;
    const int cog = blockIdx.y;
    const int hw = blockIdx.x * 1024 + threadIdx.x * 4;
    const int t = threadIdx.x;

    for (int i = t; i < 8 * Ci; i += 256)
        sW1[i] = w[(size_t)cog * 8 * Ci + i];
    __syncthreads();

    const float* ip = in + (size_t)n * Ci * 4096 + hw;
    float4 acc[8];
    #pragma unroll
    for (int co = 0; co < 8; co++) acc[co] = make_float4(0.f, 0.f, 0.f, 0.f);

    #pragma unroll 2
    for (int ci = 0; ci < Ci; ci++) {
        const float4 xv = *reinterpret_cast<const float4*>(ip + (size_t)ci * 4096);
        #pragma unroll
        for (int co = 0; co < 8; co++) {
            const float wv = sW1[co * Ci + ci];
            acc[co].x = fmaf(xv.x, wv, acc[co].x);
            acc[co].y = fmaf(xv.y, wv, acc[co].y);
            acc[co].z = fmaf(xv.z, wv, acc[co].z);
            acc[co].w = fmaf(xv.w, wv, acc[co].w);
        }
    }

    #pragma unroll
    for (int co = 0; co < 8; co++) {
        float4 v = acc[co];
        if (BIAS) {
            const float b = bias[cog * 8 + co];
            v.x += b; v.y += b; v.z += b; v.w += b;
        }
        if (RELU) {
            v.x = fmaxf(v.x, 0.f); v.y = fmaxf(v.y, 0.f);
            v.z = fmaxf(v.z, 0.f); v.w = fmaxf(v.w, 0.f);
        }
        const size_t o = ((size_t)n * Co + cog * 8 + co) * 4096 + hw;
        if (RES) {
            const float4 r = *reinterpret_cast<const float4*>(res + o);
            v.x += r.x; v.y += r.y; v.z += r.z; v.w += r.w;
        }
        *reinterpret_cast<float4*>(out + o) = v;
    }
}

// ---------------------------------------------------------------------------
// Transposed conv k4 s2 p1, parity-decomposed. Each output quad (2i..,2j..)
// reads input rows i-1..i+1, cols j-1..j+1; exactly 4 taps per output.
// Block 256 threads (16x16). Thread: 2 quads (2x4 outputs) x CO_T co.
// Block tile: 16x32 quads. grid = ((Hi/16)*(Wi/32), Co/CO_T, N)
// ---------------------------------------------------------------------------
template <int CO_T>
__global__ void __launch_bounds__(256) deconv4x4s2_tiled(
    const float* __restrict__ in, const float* __restrict__ w,
    const float* __restrict__ bias, float* __restrict__ out,
    int Ci, int Hi, int Wi, int Co)
{
    __shared__ float sIn[8][18][35];
    __shared__ float sW[8 * CO_T * 16];

    const int n = blockIdx.z;
    const int cog = blockIdx.y;
    const int ntx = Wi >> 5;
    const int tileY = blockIdx.x / ntx;
    const int tileX = blockIdx.x - tileY * ntx;
    const int i0 = tileY * 16, j0 = tileX * 32;
    const int t = threadIdx.x;
    const int tx = t & 15, ty = t >> 4;

    // acc[co][a][col] : a = output row parity, col = 0..3 (4 consecutive cols)
    float acc[CO_T][2][4];
    #pragma unroll
    for (int c = 0; c < CO_T; c++)
        #pragma unroll
        for (int a = 0; a < 2; a++)
            #pragma unroll
            for (int j = 0; j < 4; j++) acc[c][a][j] = 0.0f;

    const float* inb = in + (size_t)n * Ci * Hi * Wi;

    // tap tables: a/b = output parity; entry s: (local offset, kernel index)
    const int RR[2][2] = {{1, 0}, {2, 1}};
    const int KH[2][2] = {{1, 3}, {0, 2}};
    const int CC[2][2] = {{1, 0}, {2, 1}};
    const int KW[2][2] = {{1, 3}, {0, 2}};

    for (int cb = 0; cb < Ci; cb += 8) {
        __syncthreads();
        for (int i = t; i < 8 * 18 * 34; i += 256) {
            const int ci = i / 612;
            const int rem = i - ci * 612;
            const int r = rem / 34;
            const int c = rem - r * 34;
            const int ih = i0 - 1 + r;
            const int iw = j0 - 1 + c;
            float v = 0.0f;
            if (ih >= 0 && ih < Hi && iw >= 0 && iw < Wi)
                v = inb[(size_t)(cb + ci) * Hi * Wi + ih * Wi + iw];
            sIn[ci][r][c] = v;
        }
        for (int i = t; i < 8 * CO_T * 16; i += 256) {
            const int ci = i / (CO_T * 16);
            const int rem = i - ci * (CO_T * 16);
            const int co = rem >> 4;
            const int k = rem & 15;
            sW[i] = w[(((size_t)(cb + ci)) * Co + cog * CO_T + co) * 16 + k];
        }
        __syncthreads();

        #pragma unroll 1
        for (int ci = 0; ci < 8; ci++) {
            float iv[3][4];
            #pragma unroll
            for (int r = 0; r < 3; r++)
                #pragma unroll
                for (int c = 0; c < 4; c++)
                    iv[r][c] = sIn[ci][ty + r][2 * tx + c];
            #pragma unroll
            for (int co = 0; co < CO_T; co++) {
                const float* wp = sW + (ci * CO_T + co) * 16;
                #pragma unroll
                for (int q = 0; q < 2; q++)
                    #pragma unroll
                    for (int a = 0; a < 2; a++)
                        #pragma unroll
                        for (int b = 0; b < 2; b++) {
                            float s = acc[co][a][2 * q + b];
                            #pragma unroll
                            for (int si = 0; si < 2; si++)
                                #pragma unroll
                                for (int ti = 0; ti < 2; ti++)
                                    s = fmaf(iv[RR[a][si]][q + CC[b][ti]],
                                             wp[KH[a][si] * 4 + KW[b][ti]], s);
                            acc[co][a][2 * q + b] = s;
                        }
            }
        }
    }

    const int Ho = 2 * Hi, Wo = 2 * Wi;
    const int ow = 2 * j0 + 4 * tx;      // 16B-aligned base column
    #pragma unroll
    for (int co = 0; co < CO_T; co++) {
        const float b = bias[cog * CO_T + co];
        float* ob = out + ((size_t)n * Co + cog * CO_T + co) * Ho * Wo;
        #pragma unroll
        for (int a = 0; a < 2; a++) {
            const int oh = 2 * (i0 + ty) + a;
            float4 v = make_float4(acc[co][a][0] + b, acc[co][a][1] + b,
                                   acc[co][a][2] + b, acc[co][a][3] + b);
            *reinterpret_cast<float4*>(ob + (size_t)oh * Wo + ow) = v;
        }
    }
}

// ---------------------------------------------------------------------------
__device__ __forceinline__ float blockReduceSum(float v) {
    __shared__ float sh[32];
    #pragma unroll
    for (int o = 16; o > 0; o >>= 1) v += __shfl_down_sync(0xffffffffu, v, o);
    if ((threadIdx.x & 31) == 0) sh[threadIdx.x >> 5] = v;
    __syncthreads();
    const int nw = (blockDim.x + 31) >> 5;
    v = (threadIdx.x < (unsigned)nw) ? sh[threadIdx.x] : 0.0f;
    if (threadIdx.x < 32) {
        #pragma unroll
        for (int o = 16; o > 0; o >>= 1) v += __shfl_down_sync(0xffffffffu, v, o);
    }
    return v;
}

// ---------------------------------------------------------------------------
// Vector quantization (unchanged structure; 256-thread blocks).
// ---------------------------------------------------------------------------
#define VQ_K 512
#define VQ_D 64
#define VQ_SMEM ((VQ_K * VQ_D + VQ_K) * 4)

__global__ void __launch_bounds__(256) vq_kernel(
    const float* __restrict__ z, const float* __restrict__ cb,
    float* __restrict__ q)
{
    extern __shared__ float smem[];
    float* scb = smem;
    float* snorm = smem + VQ_K * VQ_D;

    for (int i = threadIdx.x; i < VQ_K * VQ_D; i += blockDim.x)
        scb[i] = cb[i];
    __syncthreads();
    for (int c = threadIdx.x; c < VQ_K; c += blockDim.x) {
        float s = 0.0f;
        const float* cp = scb + c * VQ_D;
        #pragma unroll 16
        for (int d = 0; d < VQ_D; d++) s = fmaf(cp[d], cp[d], s);
        snorm[c] = s;
    }
    __syncthreads();

    const int pos = blockIdx.x * blockDim.x + threadIdx.x;
    const int n = pos >> 12;
    const int hw = pos & 4095;

    float zv[VQ_D];
    const float* zp = z + (size_t)n * VQ_D * 4096 + hw;
    float zn = 0.0f;
    #pragma unroll
    for (int d = 0; d < VQ_D; d++) {
        zv[d] = zp[(size_t)d * 4096];
        zn = fmaf(zv[d], zv[d], zn);
    }

    float bestd = 3.402823466e+38f;
    int besti = 0;
    for (int c = 0; c < VQ_K; c++) {
        const float4* cp4 = reinterpret_cast<const float4*>(scb + c * VQ_D);
        float dot = 0.0f;
        #pragma unroll
        for (int d4 = 0; d4 < VQ_D / 4; d4++) {
            const float4 cv = cp4[d4];
            dot = fmaf(zv[4 * d4 + 0], cv.x, dot);
            dot = fmaf(zv[4 * d4 + 1], cv.y, dot);
            dot = fmaf(zv[4 * d4 + 2], cv.z, dot);
            dot = fmaf(zv[4 * d4 + 3], cv.w, dot);
        }
        const float dist = zn - 2.0f * dot + snorm[c];
        if (dist < bestd) { bestd = dist; besti = c; }
    }

    float lsum = 0.0f;
    const float* cp = scb + besti * VQ_D;
    float* qp = q + (size_t)n * VQ_D * 4096 + hw;
    #pragma unroll
    for (int d = 0; d < VQ_D; d++) {
        const float cv = cp[d];
        qp[(size_t)d * 4096] = cv;
        const float df = zv[d] - cv;
        lsum = fmaf(df, df, lsum);
    }
    const float bsum = blockReduceSum(lsum);
    if (threadIdx.x == 0) atomicAdd(&g_vq_loss, (double)bsum);
}

__global__ void __launch_bounds__(256) recon_loss_kernel(
    const float* __restrict__ rec, const float* __restrict__ inp, int total)
{
    float lsum = 0.0f;
    for (int i = blockIdx.x * blockDim.x + threadIdx.x; i < total;
         i += gridDim.x * blockDim.x) {
        const float d = rec[i] - inp[i];
        lsum = fmaf(d, d, lsum);
    }
    const float bsum = blockReduceSum(lsum);
    if (threadIdx.x == 0) atomicAdd(&g_rec_loss, (double)bsum);
}

__global__ void finalize_kernel(float* out, int out_size) {
    const double recon = g_rec_loss / 3145728.0;
    const double vq = g_vq_loss / 4194304.0;
    out[out_size - 2] = (float)(recon + 1.25 * vq);
    out[out_size - 1] = (float)recon;
}

// ---------------------------------------------------------------------------
extern "C" void kernel_launch(void* const* d_in, const int* in_sizes, int n_in,
                              void* d_out, int out_size)
{
    const float* inp        = (const float*)d_in[0];
    const float* enc_w1     = (const float*)d_in[1];
    const float* enc_b1     = (const float*)d_in[2];
    const float* enc_w2     = (const float*)d_in[3];
    const float* enc_b2     = (const float*)d_in[4];
    const float* enc_w3     = (const float*)d_in[5];
    const float* enc_b3     = (const float*)d_in[6];
    const float* enc_res_w1 = (const float*)d_in[7];
    const float* enc_res_w2 = (const float*)d_in[8];
    const float* vq_w       = (const float*)d_in[9];
    const float* vq_b       = (const float*)d_in[10];
    const float* codebook   = (const float*)d_in[11];
    const float* dec_w1     = (const float*)d_in[12];
    const float* dec_b1     = (const float*)d_in[13];
    const float* dec_res_w1 = (const float*)d_in[14];
    const float* dec_res_w2 = (const float*)d_in[15];
    const float* dec_w2t    = (const float*)d_in[16];
    const float* dec_b2     = (const float*)d_in[17];
    const float* dec_w3t    = (const float*)d_in[18];
    const float* dec_b3     = (const float*)d_in[19];

    float *bufA, *bufB, *bufC, *half, *zb, *qb, *d1, *d2, *eb;
    cudaGetSymbolAddress((void**)&bufA, g_bufA);
    cudaGetSymbolAddress((void**)&bufB, g_bufB);
    cudaGetSymbolAddress((void**)&bufC, g_bufC);
    cudaGetSymbolAddress((void**)&half, g_half);
    cudaGetSymbolAddress((void**)&zb, g_z);
    cudaGetSymbolAddress((void**)&qb, g_q);
    cudaGetSymbolAddress((void**)&d1, g_d1);
    cudaGetSymbolAddress((void**)&d2, g_d2);
    cudaGetSymbolAddress((void**)&eb, g_e);

    cudaFuncSetAttribute(vq_kernel, cudaFuncAttributeMaxDynamicSharedMemorySize,
                         VQ_SMEM);
    cudaFuncSetAttribute(conv4x4s2_tiled,
                         cudaFuncAttributeMaxDynamicSharedMemorySize, K4_SMEM);

    zero_losses_kernel<<<1, 1>>>();

    // ---- Encoder ----
    // enc1: 3->64, 256->128
    conv4x4s2_tiled<<<dim3(16, 8, NB), 256, K4_SMEM>>>(
        inp, enc_w1, enc_b1, bufA, 3, 256, 256, 64, 128, 128);
    // enc2: 64->128, 128->64
    conv4x4s2_tiled<<<dim3(4, 16, NB), 256, K4_SMEM>>>(
        bufA, enc_w2, enc_b2, bufB, 64, 128, 128, 128, 64, 64);
    // enc3: 128->128, 3x3
    conv3x3_tiled<false, true><<<dim3(4, 16, NB), 256>>>(
        bufB, enc_w3, enc_b3, bufC, 128, 128);

    // enc resblocks
    {
        float* cur = bufC;
        float* alt = bufB;
        for (int i = 0; i < 3; i++) {
            conv3x3_tiled<true, false><<<dim3(4, 8, NB), 256>>>(
                cur, enc_res_w1 + (size_t)i * 64 * 128 * 9, nullptr, half,
                128, 64);
            conv1x1_k<true, false, true><<<dim3(4, 16, NB), 256>>>(
                half, enc_res_w2 + (size_t)i * 128 * 64, nullptr, cur, alt,
                64, 128);
            float* t = cur; cur = alt; alt = t;
        }
        conv1x1_k<false, true, false><<<dim3(4, 8, NB), 256>>>(
            cur, vq_w, vq_b, nullptr, zb, 128, 64);
    }

    // ---- VQ ----
    vq_kernel<<<256, 256, VQ_SMEM>>>(zb, codebook, qb);

    // ---- Decoder ----
    conv3x3_tiled<false, true><<<dim3(4, 8, NB), 256>>>(
        qb, dec_w1, dec_b1, d1, 64, 64);
    {
        float* cur = d1;
        float* alt = d2;
        for (int i = 0; i < 3; i++) {
            conv3x3_tiled<true, false><<<dim3(4, 4, NB), 256>>>(
                cur, dec_res_w1 + (size_t)i * 32 * 64 * 9, nullptr, half,
                64, 32);
            conv1x1_k<true, false, true><<<dim3(4, 8, NB), 256>>>(
                half, dec_res_w2 + (size_t)i * 64 * 32, nullptr, cur, alt,
                32, 64);
            float* t = cur; cur = alt; alt = t;
        }
        // deconv1: 64->32, 64->128
        deconv4x4s2_tiled<4><<<dim3(8, 8, NB), 256>>>(
            cur, dec_w2t, dec_b2, eb, 64, 64, 64, 32);
    }
    // deconv2: 32->3, 128->256
    deconv4x4s2_tiled<3><<<dim3(32, 1, NB), 256>>>(
        eb, dec_w3t, dec_b3, (float*)d_out, 32, 128, 128, 3);

    // ---- Losses ----
    recon_loss_kernel<<<1024, 256>>>((const float*)d_out, inp, 3145728);
    finalize_kernel<<<1, 1>>>((float*)d_out, out_size);
}

// round 4
// speedup vs baseline: 3.5138x; 1.0857x over previous
#include <cuda_runtime.h>
#include <cstdint>

// ---------------------------------------------------------------------------
// VQ-VAE forward, sm_100a. Round 3: vectorized-smem tiled direct convolutions.
// ---------------------------------------------------------------------------

#define NB 16

__device__ float g_bufA[(size_t)NB * 64 * 128 * 128];
__device__ float g_bufB[(size_t)NB * 128 * 64 * 64];
__device__ float g_bufC[(size_t)NB * 128 * 64 * 64];
__device__ float g_half[(size_t)NB * 64 * 64 * 64];
__device__ float g_z[(size_t)NB * 64 * 64 * 64];
__device__ float g_q[(size_t)NB * 64 * 64 * 64];
__device__ float g_d1[(size_t)NB * 64 * 64 * 64];
__device__ float g_d2[(size_t)NB * 64 * 64 * 64];
__device__ float g_e[(size_t)NB * 32 * 128 * 128];
__device__ double g_vq_loss;
__device__ double g_rec_loss;

__global__ void zero_losses_kernel() {
    g_vq_loss = 0.0;
    g_rec_loss = 0.0;
}

// ---------------------------------------------------------------------------
// 3x3 conv, stride 1, pad 1, H=W=64. Block 256 (16x16).
// Block tile: 32x32 out x 8 co. Thread: 2x2 out x 8 co.
// sIn rows padded to 36 floats (16B aligned). sW padded to 12 per (co,ci).
// grid = (4, Co/8, N)
// ---------------------------------------------------------------------------
template <bool RELU, bool BIAS>
__global__ void __launch_bounds__(256) conv3x3_tiled(
    const float* __restrict__ in, const float* __restrict__ w,
    const float* __restrict__ bias, float* __restrict__ out,
    int Ci, int Co)
{
    __shared__ float sIn[8][34][36];
    __shared__ float sW[8][8][12];

    const int n = blockIdx.z;
    const int cog = blockIdx.y;
    const int oh0 = (blockIdx.x >> 1) * 32;
    const int ow0 = (blockIdx.x & 1) * 32;
    const int t = threadIdx.x;
    const int tx = t & 15, ty = t >> 4;

    float acc[8][4];
    #pragma unroll
    for (int i = 0; i < 8; i++)
        #pragma unroll
        for (int j = 0; j < 4; j++) acc[i][j] = 0.0f;

    const float* inb = in + (size_t)n * Ci * 4096;

    for (int cb = 0; cb < Ci; cb += 8) {
        __syncthreads();
        for (int i = t; i < 8 * 34 * 34; i += 256) {
            const int ci = i / 1156;
            const int rem = i - ci * 1156;
            const int r = rem / 34;
            const int c = rem - r * 34;
            const int ih = oh0 - 1 + r;
            const int iw = ow0 - 1 + c;
            float v = 0.0f;
            if (ih >= 0 && ih < 64 && iw >= 0 && iw < 64)
                v = inb[(size_t)(cb + ci) * 4096 + ih * 64 + iw];
            sIn[ci][r][c] = v;
        }
        for (int i = t; i < 8 * 8 * 9; i += 256) {
            const int co = i / 72;
            const int rem = i - co * 72;
            const int ci = rem / 9;
            const int k = rem - ci * 9;
            sW[co][ci][k] = w[(((size_t)(cog * 8 + co)) * Ci + cb + ci) * 9 + k];
        }
        __syncthreads();

        #pragma unroll 1
        for (int ci = 0; ci < 8; ci++) {
            float iv[4][4];
            #pragma unroll
            for (int r = 0; r < 4; r++) {
                const float2* rp = reinterpret_cast<const float2*>(
                    &sIn[ci][2 * ty + r][2 * tx]);
                const float2 a = rp[0], b = rp[1];
                iv[r][0] = a.x; iv[r][1] = a.y;
                iv[r][2] = b.x; iv[r][3] = b.y;
            }
            #pragma unroll
            for (int co = 0; co < 8; co++) {
                const float4* wq = reinterpret_cast<const float4*>(&sW[co][ci][0]);
                const float4 w0 = wq[0], w1 = wq[1];
                const float w8 = sW[co][ci][8];
                float wv[9] = {w0.x, w0.y, w0.z, w0.w, w1.x, w1.y, w1.z, w1.w, w8};
                #pragma unroll
                for (int r2 = 0; r2 < 2; r2++)
                    #pragma unroll
                    for (int c2 = 0; c2 < 2; c2++) {
                        float a = acc[co][r2 * 2 + c2];
                        #pragma unroll
                        for (int kh = 0; kh < 3; kh++)
                            #pragma unroll
                            for (int kw = 0; kw < 3; kw++)
                                a = fmaf(iv[r2 + kh][c2 + kw], wv[kh * 3 + kw], a);
                        acc[co][r2 * 2 + c2] = a;
                    }
            }
        }
    }

    float* outb = out + ((size_t)n * Co + cog * 8) * 4096;
    #pragma unroll
    for (int co = 0; co < 8; co++) {
        const float b = BIAS ? bias[cog * 8 + co] : 0.0f;
        #pragma unroll
        for (int r2 = 0; r2 < 2; r2++) {
            const int oh = oh0 + 2 * ty + r2;
            float v0 = acc[co][r2 * 2 + 0] + b;
            float v1 = acc[co][r2 * 2 + 1] + b;
            if (RELU) { v0 = fmaxf(v0, 0.0f); v1 = fmaxf(v1, 0.0f); }
            *reinterpret_cast<float2*>(
                outb + (size_t)co * 4096 + oh * 64 + ow0 + 2 * tx) =
                make_float2(v0, v1);
        }
    }
}

// ---------------------------------------------------------------------------
// 4x4 conv, stride 2, pad 1. Block 256 (16x16).
// Block tile: 32x32 out x 8 co. Thread: 2x2 out x 8 co.
// sIn rows padded to 68 floats (16B aligned). grid = (tiles, Co/8, N)
// ---------------------------------------------------------------------------
#define K4_SMEM ((4 * 66 * 68 + 8 * 4 * 16) * 4)

__global__ void __launch_bounds__(256) conv4x4s2_tiled(
    const float* __restrict__ in, const float* __restrict__ w,
    const float* __restrict__ bias, float* __restrict__ out,
    int Ci, int Hi, int Wi, int Co, int Ho, int Wo)
{
    extern __shared__ float sm[];
    float (*sIn)[66][68] = reinterpret_cast<float(*)[66][68]>(sm);
    float* sWp = sm + 4 * 66 * 68;

    const int n = blockIdx.z;
    const int cog = blockIdx.y;
    const int ntx = Wo >> 5;
    const int tileY = blockIdx.x / ntx;
    const int tileX = blockIdx.x - tileY * ntx;
    const int oh0 = tileY * 32, ow0 = tileX * 32;
    const int t = threadIdx.x;
    const int tx = t & 15, ty = t >> 4;

    float acc[8][4];
    #pragma unroll
    for (int i = 0; i < 8; i++)
        #pragma unroll
        for (int j = 0; j < 4; j++) acc[i][j] = 0.0f;

    const float* inb = in + (size_t)n * Ci * Hi * Wi;

    for (int cb = 0; cb < Ci; cb += 4) {
        __syncthreads();
        for (int i = t; i < 4 * 66 * 66; i += 256) {
            const int ci = i / 4356;
            const int rem = i - ci * 4356;
            const int r = rem / 66;
            const int c = rem - r * 66;
            const int ih = oh0 * 2 - 1 + r;
            const int iw = ow0 * 2 - 1 + c;
            const int cig = cb + ci;
            float v = 0.0f;
            if (cig < Ci && ih >= 0 && ih < Hi && iw >= 0 && iw < Wi)
                v = inb[(size_t)cig * Hi * Wi + ih * Wi + iw];
            sIn[ci][r][c] = v;
        }
        for (int i = t; i < 8 * 4 * 16; i += 256) {
            const int co = i >> 6;
            const int rem = i & 63;
            const int ci = rem >> 4;
            const int k = rem & 15;
            const int cig = cb + ci;
            sWp[i] = (cig < Ci)
                ? w[(((size_t)(cog * 8 + co)) * Ci + cig) * 16 + k] : 0.0f;
        }
        __syncthreads();

        #pragma unroll 1
        for (int ci = 0; ci < 4; ci++) {
            float iv[6][6];
            #pragma unroll
            for (int r = 0; r < 6; r++) {
                const float* rb = &sIn[ci][4 * ty + r][4 * tx];
                const float4 a = *reinterpret_cast<const float4*>(rb);
                const float2 b = *reinterpret_cast<const float2*>(rb + 4);
                iv[r][0] = a.x; iv[r][1] = a.y; iv[r][2] = a.z; iv[r][3] = a.w;
                iv[r][4] = b.x; iv[r][5] = b.y;
            }
            #pragma unroll
            for (int co = 0; co < 8; co++) {
                const float4* wq = reinterpret_cast<const float4*>(
                    sWp + (co * 4 + ci) * 16);
                const float4 q0 = wq[0], q1 = wq[1], q2 = wq[2], q3 = wq[3];
                float wv[16] = {q0.x, q0.y, q0.z, q0.w, q1.x, q1.y, q1.z, q1.w,
                                q2.x, q2.y, q2.z, q2.w, q3.x, q3.y, q3.z, q3.w};
                #pragma unroll
                for (int r2 = 0; r2 < 2; r2++)
                    #pragma unroll
                    for (int c2 = 0; c2 < 2; c2++) {
                        float a = acc[co][r2 * 2 + c2];
                        #pragma unroll
                        for (int kh = 0; kh < 4; kh++)
                            #pragma unroll
                            for (int kw = 0; kw < 4; kw++)
                                a = fmaf(iv[2 * r2 + kh][2 * c2 + kw],
                                         wv[kh * 4 + kw], a);
                        acc[co][r2 * 2 + c2] = a;
                    }
            }
        }
    }

    #pragma unroll
    for (int co = 0; co < 8; co++) {
        const float b = bias[cog * 8 + co];
        float* ob = out + ((size_t)n * Co + cog * 8 + co) * Ho * Wo;
        #pragma unroll
        for (int r2 = 0; r2 < 2; r2++) {
            const int oh = oh0 + 2 * ty + r2;
            *reinterpret_cast<float2*>(ob + (size_t)oh * Wo + ow0 + 2 * tx) =
                make_float2(acc[co][r2 * 2 + 0] + b, acc[co][r2 * 2 + 1] + b);
        }
    }
}

// ---------------------------------------------------------------------------
// 1x1 conv. Block 256; thread: 4 hw x 8 co. grid = (4, Co/8, N)
// ---------------------------------------------------------------------------
template <bool RELU, bool BIAS, bool RES>
__global__ void __launch_bounds__(256) conv1x1_k(
    const float* __restrict__ in, const float* __restrict__ w,
    const float* __restrict__ bias, const float* __restrict__ res,
    float* __restrict__ out, int Ci, int Co)
{
    __shared__ float sW1[8 * 128];
    const int n = blockIdx.z;
    const int cog = blockIdx.y;
    const int hw = blockIdx.x * 1024 + threadIdx.x * 4;
    const int t = threadIdx.x;

    for (int i = t; i < 8 * Ci; i += 256)
        sW1[i] = w[(size_t)cog * 8 * Ci + i];
    __syncthreads();

    const float* ip = in + (size_t)n * Ci * 4096 + hw;
    float4 acc[8];
    #pragma unroll
    for (int co = 0; co < 8; co++) acc[co] = make_float4(0.f, 0.f, 0.f, 0.f);

    #pragma unroll 2
    for (int ci = 0; ci < Ci; ci++) {
        const float4 xv = *reinterpret_cast<const float4*>(ip + (size_t)ci * 4096);
        #pragma unroll
        for (int co = 0; co < 8; co++) {
            const float wv = sW1[co * Ci + ci];
            acc[co].x = fmaf(xv.x, wv, acc[co].x);
            acc[co].y = fmaf(xv.y, wv, acc[co].y);
            acc[co].z = fmaf(xv.z, wv, acc[co].z);
            acc[co].w = fmaf(xv.w, wv, acc[co].w);
        }
    }

    #pragma unroll
    for (int co = 0; co < 8; co++) {
        float4 v = acc[co];
        if (BIAS) {
            const float b = bias[cog * 8 + co];
            v.x += b; v.y += b; v.z += b; v.w += b;
        }
        if (RELU) {
            v.x = fmaxf(v.x, 0.f); v.y = fmaxf(v.y, 0.f);
            v.z = fmaxf(v.z, 0.f); v.w = fmaxf(v.w, 0.f);
        }
        const size_t o = ((size_t)n * Co + cog * 8 + co) * 4096 + hw;
        if (RES) {
            const float4 r = *reinterpret_cast<const float4*>(res + o);
            v.x += r.x; v.y += r.y; v.z += r.z; v.w += r.w;
        }
        *reinterpret_cast<float4*>(out + o) = v;
    }
}

// ---------------------------------------------------------------------------
// Transposed conv k4 s2 p1, parity-decomposed. Block 256 (16x16).
// Thread: 2 quads (2x4 outputs) x CO_T co. sIn rows padded to 36.
// grid = ((Hi/16)*(Wi/32), Co/CO_T, N)
// ---------------------------------------------------------------------------
template <int CO_T>
__global__ void __launch_bounds__(256) deconv4x4s2_tiled(
    const float* __restrict__ in, const float* __restrict__ w,
    const float* __restrict__ bias, float* __restrict__ out,
    int Ci, int Hi, int Wi, int Co)
{
    __shared__ float sIn[8][18][36];
    __shared__ float sW[8 * CO_T * 16];

    const int n = blockIdx.z;
    const int cog = blockIdx.y;
    const int ntx = Wi >> 5;
    const int tileY = blockIdx.x / ntx;
    const int tileX = blockIdx.x - tileY * ntx;
    const int i0 = tileY * 16, j0 = tileX * 32;
    const int t = threadIdx.x;
    const int tx = t & 15, ty = t >> 4;

    float acc[CO_T][2][4];
    #pragma unroll
    for (int c = 0; c < CO_T; c++)
        #pragma unroll
        for (int a = 0; a < 2; a++)
            #pragma unroll
            for (int j = 0; j < 4; j++) acc[c][a][j] = 0.0f;

    const float* inb = in + (size_t)n * Ci * Hi * Wi;

    const int RR[2][2] = {{1, 0}, {2, 1}};
    const int KH[2][2] = {{1, 3}, {0, 2}};
    const int CC[2][2] = {{1, 0}, {2, 1}};
    const int KW[2][2] = {{1, 3}, {0, 2}};

    for (int cb = 0; cb < Ci; cb += 8) {
        __syncthreads();
        for (int i = t; i < 8 * 18 * 34; i += 256) {
            const int ci = i / 612;
            const int rem = i - ci * 612;
            const int r = rem / 34;
            const int c = rem - r * 34;
            const int ih = i0 - 1 + r;
            const int iw = j0 - 1 + c;
            float v = 0.0f;
            if (ih >= 0 && ih < Hi && iw >= 0 && iw < Wi)
                v = inb[(size_t)(cb + ci) * Hi * Wi + ih * Wi + iw];
            sIn[ci][r][c] = v;
        }
        for (int i = t; i < 8 * CO_T * 16; i += 256) {
            const int ci = i / (CO_T * 16);
            const int rem = i - ci * (CO_T * 16);
            const int co = rem >> 4;
            const int k = rem & 15;
            sW[i] = w[(((size_t)(cb + ci)) * Co + cog * CO_T + co) * 16 + k];
        }
        __syncthreads();

        #pragma unroll 1
        for (int ci = 0; ci < 8; ci++) {
            float iv[3][4];
            #pragma unroll
            for (int r = 0; r < 3; r++) {
                const float2* rp = reinterpret_cast<const float2*>(
                    &sIn[ci][ty + r][2 * tx]);
                const float2 a = rp[0], b = rp[1];
                iv[r][0] = a.x; iv[r][1] = a.y; iv[r][2] = b.x; iv[r][3] = b.y;
            }
            #pragma unroll
            for (int co = 0; co < CO_T; co++) {
                const float4* wq = reinterpret_cast<const float4*>(
                    sW + (ci * CO_T + co) * 16);
                const float4 q0 = wq[0], q1 = wq[1], q2 = wq[2], q3 = wq[3];
                float wv[16] = {q0.x, q0.y, q0.z, q0.w, q1.x, q1.y, q1.z, q1.w,
                                q2.x, q2.y, q2.z, q2.w, q3.x, q3.y, q3.z, q3.w};
                #pragma unroll
                for (int q = 0; q < 2; q++)
                    #pragma unroll
                    for (int a = 0; a < 2; a++)
                        #pragma unroll
                        for (int b = 0; b < 2; b++) {
                            float s = acc[co][a][2 * q + b];
                            #pragma unroll
                            for (int si = 0; si < 2; si++)
                                #pragma unroll
                                for (int ti = 0; ti < 2; ti++)
                                    s = fmaf(iv[RR[a][si]][q + CC[b][ti]],
                                             wv[KH[a][si] * 4 + KW[b][ti]], s);
                            acc[co][a][2 * q + b] = s;
                        }
            }
        }
    }

    const int Ho = 2 * Hi, Wo = 2 * Wi;
    const int ow = 2 * j0 + 4 * tx;
    #pragma unroll
    for (int co = 0; co < CO_T; co++) {
        const float b = bias[cog * CO_T + co];
        float* ob = out + ((size_t)n * Co + cog * CO_T + co) * Ho * Wo;
        #pragma unroll
        for (int a = 0; a < 2; a++) {
            const int oh = 2 * (i0 + ty) + a;
            *reinterpret_cast<float4*>(ob + (size_t)oh * Wo + ow) =
                make_float4(acc[co][a][0] + b, acc[co][a][1] + b,
                            acc[co][a][2] + b, acc[co][a][3] + b);
        }
    }
}

// ---------------------------------------------------------------------------
__device__ __forceinline__ float blockReduceSum(float v) {
    __shared__ float sh[32];
    #pragma unroll
    for (int o = 16; o > 0; o >>= 1) v += __shfl_down_sync(0xffffffffu, v, o);
    if ((threadIdx.x & 31) == 0) sh[threadIdx.x >> 5] = v;
    __syncthreads();
    const int nw = (blockDim.x + 31) >> 5;
    v = (threadIdx.x < (unsigned)nw) ? sh[threadIdx.x] : 0.0f;
    if (threadIdx.x < 32) {
        #pragma unroll
        for (int o = 16; o > 0; o >>= 1) v += __shfl_down_sync(0xffffffffu, v, o);
    }
    return v;
}

#define VQ_K 512
#define VQ_D 64
#define VQ_SMEM ((VQ_K * VQ_D + VQ_K) * 4)

__global__ void __launch_bounds__(256) vq_kernel(
    const float* __restrict__ z, const float* __restrict__ cb,
    float* __restrict__ q)
{
    extern __shared__ float smem[];
    float* scb = smem;
    float* snorm = smem + VQ_K * VQ_D;

    for (int i = threadIdx.x; i < VQ_K * VQ_D; i += blockDim.x)
        scb[i] = cb[i];
    __syncthreads();
    for (int c = threadIdx.x; c < VQ_K; c += blockDim.x) {
        float s = 0.0f;
        const float* cp = scb + c * VQ_D;
        #pragma unroll 16
        for (int d = 0; d < VQ_D; d++) s = fmaf(cp[d], cp[d], s);
        snorm[c] = s;
    }
    __syncthreads();

    const int pos = blockIdx.x * blockDim.x + threadIdx.x;
    const int n = pos >> 12;
    const int hw = pos & 4095;

    float zv[VQ_D];
    const float* zp = z + (size_t)n * VQ_D * 4096 + hw;
    float zn = 0.0f;
    #pragma unroll
    for (int d = 0; d < VQ_D; d++) {
        zv[d] = zp[(size_t)d * 4096];
        zn = fmaf(zv[d], zv[d], zn);
    }

    float bestd = 3.402823466e+38f;
    int besti = 0;
    for (int c = 0; c < VQ_K; c++) {
        const float4* cp4 = reinterpret_cast<const float4*>(scb + c * VQ_D);
        float dot = 0.0f;
        #pragma unroll
        for (int d4 = 0; d4 < VQ_D / 4; d4++) {
            const float4 cv = cp4[d4];
            dot = fmaf(zv[4 * d4 + 0], cv.x, dot);
            dot = fmaf(zv[4 * d4 + 1], cv.y, dot);
            dot = fmaf(zv[4 * d4 + 2], cv.z, dot);
            dot = fmaf(zv[4 * d4 + 3], cv.w, dot);
        }
        const float dist = zn - 2.0f * dot + snorm[c];
        if (dist < bestd) { bestd = dist; besti = c; }
    }

    float lsum = 0.0f;
    const float* cp = scb + besti * VQ_D;
    float* qp = q + (size_t)n * VQ_D * 4096 + hw;
    #pragma unroll
    for (int d = 0; d < VQ_D; d++) {
        const float cv = cp[d];
        qp[(size_t)d * 4096] = cv;
        const float df = zv[d] - cv;
        lsum = fmaf(df, df, lsum);
    }
    const float bsum = blockReduceSum(lsum);
    if (threadIdx.x == 0) atomicAdd(&g_vq_loss, (double)bsum);
}

__global__ void __launch_bounds__(256) recon_loss_kernel(
    const float* __restrict__ rec, const float* __restrict__ inp, int total)
{
    float lsum = 0.0f;
    for (int i = blockIdx.x * blockDim.x + threadIdx.x; i < total;
         i += gridDim.x * blockDim.x) {
        const float d = rec[i] - inp[i];
        lsum = fmaf(d, d, lsum);
    }
    const float bsum = blockReduceSum(lsum);
    if (threadIdx.x == 0) atomicAdd(&g_rec_loss, (double)bsum);
}

__global__ void finalize_kernel(float* out, int out_size) {
    const double recon = g_rec_loss / 3145728.0;
    const double vq = g_vq_loss / 4194304.0;
    out[out_size - 2] = (float)(recon + 1.25 * vq);
    out[out_size - 1] = (float)recon;
}

// ---------------------------------------------------------------------------
extern "C" void kernel_launch(void* const* d_in, const int* in_sizes, int n_in,
                              void* d_out, int out_size)
{
    const float* inp        = (const float*)d_in[0];
    const float* enc_w1     = (const float*)d_in[1];
    const float* enc_b1     = (const float*)d_in[2];
    const float* enc_w2     = (const float*)d_in[3];
    const float* enc_b2     = (const float*)d_in[4];
    const float* enc_w3     = (const float*)d_in[5];
    const float* enc_b3     = (const float*)d_in[6];
    const float* enc_res_w1 = (const float*)d_in[7];
    const float* enc_res_w2 = (const float*)d_in[8];
    const float* vq_w       = (const float*)d_in[9];
    const float* vq_b       = (const float*)d_in[10];
    const float* codebook   = (const float*)d_in[11];
    const float* dec_w1     = (const float*)d_in[12];
    const float* dec_b1     = (const float*)d_in[13];
    const float* dec_res_w1 = (const float*)d_in[14];
    const float* dec_res_w2 = (const float*)d_in[15];
    const float* dec_w2t    = (const float*)d_in[16];
    const float* dec_b2     = (const float*)d_in[17];
    const float* dec_w3t    = (const float*)d_in[18];
    const float* dec_b3     = (const float*)d_in[19];

    float *bufA, *bufB, *bufC, *half, *zb, *qb, *d1, *d2, *eb;
    cudaGetSymbolAddress((void**)&bufA, g_bufA);
    cudaGetSymbolAddress((void**)&bufB, g_bufB);
    cudaGetSymbolAddress((void**)&bufC, g_bufC);
    cudaGetSymbolAddress((void**)&half, g_half);
    cudaGetSymbolAddress((void**)&zb, g_z);
    cudaGetSymbolAddress((void**)&qb, g_q);
    cudaGetSymbolAddress((void**)&d1, g_d1);
    cudaGetSymbolAddress((void**)&d2, g_d2);
    cudaGetSymbolAddress((void**)&eb, g_e);

    cudaFuncSetAttribute(vq_kernel, cudaFuncAttributeMaxDynamicSharedMemorySize,
                         VQ_SMEM);
    cudaFuncSetAttribute(conv4x4s2_tiled,
                         cudaFuncAttributeMaxDynamicSharedMemorySize, K4_SMEM);

    zero_losses_kernel<<<1, 1>>>();

    // ---- Encoder ----
    conv4x4s2_tiled<<<dim3(16, 8, NB), 256, K4_SMEM>>>(
        inp, enc_w1, enc_b1, bufA, 3, 256, 256, 64, 128, 128);
    conv4x4s2_tiled<<<dim3(4, 16, NB), 256, K4_SMEM>>>(
        bufA, enc_w2, enc_b2, bufB, 64, 128, 128, 128, 64, 64);
    conv3x3_tiled<false, true><<<dim3(4, 16, NB), 256>>>(
        bufB, enc_w3, enc_b3, bufC, 128, 128);

    {
        float* cur = bufC;
        float* alt = bufB;
        for (int i = 0; i < 3; i++) {
            conv3x3_tiled<true, false><<<dim3(4, 8, NB), 256>>>(
                cur, enc_res_w1 + (size_t)i * 64 * 128 * 9, nullptr, half,
                128, 64);
            conv1x1_k<true, false, true><<<dim3(4, 16, NB), 256>>>(
                half, enc_res_w2 + (size_t)i * 128 * 64, nullptr, cur, alt,
                64, 128);
            float* t = cur; cur = alt; alt = t;
        }
        conv1x1_k<false, true, false><<<dim3(4, 8, NB), 256>>>(
            cur, vq_w, vq_b, nullptr, zb, 128, 64);
    }

    // ---- VQ ----
    vq_kernel<<<256, 256, VQ_SMEM>>>(zb, codebook, qb);

    // ---- Decoder ----
    conv3x3_tiled<false, true><<<dim3(4, 8, NB), 256>>>(
        qb, dec_w1, dec_b1, d1, 64, 64);
    {
        float* cur = d1;
        float* alt = d2;
        for (int i = 0; i < 3; i++) {
            conv3x3_tiled<true, false><<<dim3(4, 4, NB), 256>>>(
                cur, dec_res_w1 + (size_t)i * 32 * 64 * 9, nullptr, half,
                64, 32);
            conv1x1_k<true, false, true><<<dim3(4, 8, NB), 256>>>(
                half, dec_res_w2 + (size_t)i * 64 * 32, nullptr, cur, alt,
                32, 64);
            float* t = cur; cur = alt; alt = t;
        }
        deconv4x4s2_tiled<4><<<dim3(8, 8, NB), 256>>>(
            cur, dec_w2t, dec_b2, eb, 64, 64, 64, 32);
    }
    deconv4x4s2_tiled<3><<<dim3(32, 1, NB), 256>>>(
        eb, dec_w3t, dec_b3, (float*)d_out, 32, 128, 128, 3);

    // ---- Losses ----
    recon_loss_kernel<<<1024, 256>>>((const float*)d_out, inp, 3145728);
    finalize_kernel<<<1, 1>>>((float*)d_out, out_size);
}

// round 5
// speedup vs baseline: 4.0777x; 1.1605x over previous
#include <cuda_runtime.h>
#include <cstdint>

// ---------------------------------------------------------------------------
// VQ-VAE forward, sm_100a. Round 4: big-tile 3x3 convs (32x64 block tile,
// 2x4x8 thread tile, div-free staging), rest as round 3.
// ---------------------------------------------------------------------------

#define NB 16

__device__ float g_bufA[(size_t)NB * 64 * 128 * 128];
__device__ float g_bufB[(size_t)NB * 128 * 64 * 64];
__device__ float g_bufC[(size_t)NB * 128 * 64 * 64];
__device__ float g_half[(size_t)NB * 64 * 64 * 64];
__device__ float g_z[(size_t)NB * 64 * 64 * 64];
__device__ float g_q[(size_t)NB * 64 * 64 * 64];
__device__ float g_d1[(size_t)NB * 64 * 64 * 64];
__device__ float g_d2[(size_t)NB * 64 * 64 * 64];
__device__ float g_e[(size_t)NB * 32 * 128 * 128];
__device__ double g_vq_loss;
__device__ double g_rec_loss;

__global__ void zero_losses_kernel() {
    g_vq_loss = 0.0;
    g_rec_loss = 0.0;
}

// ---------------------------------------------------------------------------
// 3x3 conv, stride 1, pad 1, H=W=64. Block 256 threads (16x16).
// Block tile: 32 rows x 64 cols (full width) x 8 co.
// Thread tile: 2 rows x 4 cols x 8 co = 64 accumulators.
// smem: sIn[8][34][68] (col 0 = input col -1, col 65 = input col 64, both
// always zero -> written once), sW[8][8][12]. grid = (2, Co/8, N).
// ---------------------------------------------------------------------------
#define C3_SMEM ((8 * 34 * 68 + 8 * 8 * 12) * 4)

template <bool RELU, bool BIAS>
__global__ void __launch_bounds__(256, 2) conv3x3_big(
    const float* __restrict__ in, const float* __restrict__ w,
    const float* __restrict__ bias, float* __restrict__ out,
    int Ci, int Co)
{
    extern __shared__ float sm[];
    float (*sIn)[34][68] = reinterpret_cast<float(*)[34][68]>(sm);
    float (*sW)[8][12] = reinterpret_cast<float(*)[8][12]>(sm + 8 * 34 * 68);

    const int n = blockIdx.z;
    const int cog = blockIdx.y;
    const int oh0 = blockIdx.x * 32;
    const int t = threadIdx.x;
    const int tx = t & 15, ty = t >> 4;

    // zero halo columns once (input cols -1 and 64 are always OOB)
    if (t < 34) {
        #pragma unroll
        for (int ci = 0; ci < 8; ci++) {
            sIn[ci][t][0] = 0.0f;
            sIn[ci][t][65] = 0.0f;
        }
    }

    float acc[8][8];
    #pragma unroll
    for (int i = 0; i < 8; i++)
        #pragma unroll
        for (int j = 0; j < 8; j++) acc[i][j] = 0.0f;

    const float* inb = in + (size_t)n * Ci * 4096;
    const int c64 = t & 63;   // staging column 0..63
    const int r4 = t >> 6;    // staging row phase 0..3

    for (int cb = 0; cb < Ci; cb += 8) {
        __syncthreads();
        // stage inputs: 8 ci x rows (oh0-1 .. oh0+32) x cols 0..63
        #pragma unroll
        for (int ci = 0; ci < 8; ci++) {
            const float* g = inb + (size_t)(cb + ci) * 4096 + c64;
            #pragma unroll
            for (int rb = 0; rb < 36; rb += 4) {
                const int r = rb + r4;
                if (r < 34) {
                    const int ih = oh0 - 1 + r;
                    float v = 0.0f;
                    if (ih >= 0 && ih < 64) v = g[ih * 64];
                    sIn[ci][r][c64 + 1] = v;
                }
            }
        }
        // stage weights: 8 co x 8 ci x 9 (padded to 12)
        for (int i = t; i < 576; i += 256) {
            const int co = i / 72;
            const int rem = i - co * 72;
            const int ci = rem / 9;
            const int k = rem - ci * 9;
            sW[co][ci][k] = w[(((size_t)(cog * 8 + co)) * Ci + cb + ci) * 9 + k];
        }
        __syncthreads();

        #pragma unroll 1
        for (int ci = 0; ci < 8; ci++) {
            float iv[4][6];
            #pragma unroll
            for (int r = 0; r < 4; r++) {
                const float* rp = &sIn[ci][2 * ty + r][4 * tx];
                const float4 a = *reinterpret_cast<const float4*>(rp);
                const float2 b = *reinterpret_cast<const float2*>(rp + 4);
                iv[r][0] = a.x; iv[r][1] = a.y; iv[r][2] = a.z;
                iv[r][3] = a.w; iv[r][4] = b.x; iv[r][5] = b.y;
            }
            #pragma unroll
            for (int co = 0; co < 8; co++) {
                const float4* wq = reinterpret_cast<const float4*>(&sW[co][ci][0]);
                const float4 w0 = wq[0], w1 = wq[1];
                const float w8 = sW[co][ci][8];
                const float wv[9] = {w0.x, w0.y, w0.z, w0.w,
                                     w1.x, w1.y, w1.z, w1.w, w8};
                #pragma unroll
                for (int r2 = 0; r2 < 2; r2++)
                    #pragma unroll
                    for (int c2 = 0; c2 < 4; c2++) {
                        float a = acc[co][r2 * 4 + c2];
                        #pragma unroll
                        for (int kh = 0; kh < 3; kh++)
                            #pragma unroll
                            for (int kw = 0; kw < 3; kw++)
                                a = fmaf(iv[r2 + kh][c2 + kw],
                                         wv[kh * 3 + kw], a);
                        acc[co][r2 * 4 + c2] = a;
                    }
            }
        }
    }

    float* outb = out + ((size_t)n * Co + cog * 8) * 4096;
    #pragma unroll
    for (int co = 0; co < 8; co++) {
        const float b = BIAS ? bias[cog * 8 + co] : 0.0f;
        #pragma unroll
        for (int r2 = 0; r2 < 2; r2++) {
            const int oh = oh0 + 2 * ty + r2;
            float4 v = make_float4(acc[co][r2 * 4 + 0] + b,
                                   acc[co][r2 * 4 + 1] + b,
                                   acc[co][r2 * 4 + 2] + b,
                                   acc[co][r2 * 4 + 3] + b);
            if (RELU) {
                v.x = fmaxf(v.x, 0.f); v.y = fmaxf(v.y, 0.f);
                v.z = fmaxf(v.z, 0.f); v.w = fmaxf(v.w, 0.f);
            }
            *reinterpret_cast<float4*>(
                outb + (size_t)co * 4096 + oh * 64 + 4 * tx) = v;
        }
    }
}

// ---------------------------------------------------------------------------
// 4x4 conv, stride 2, pad 1 (round-3 version).
// ---------------------------------------------------------------------------
#define K4_SMEM ((4 * 66 * 68 + 8 * 4 * 16) * 4)

__global__ void __launch_bounds__(256) conv4x4s2_tiled(
    const float* __restrict__ in, const float* __restrict__ w,
    const float* __restrict__ bias, float* __restrict__ out,
    int Ci, int Hi, int Wi, int Co, int Ho, int Wo)
{
    extern __shared__ float sm[];
    float (*sIn)[66][68] = reinterpret_cast<float(*)[66][68]>(sm);
    float* sWp = sm + 4 * 66 * 68;

    const int n = blockIdx.z;
    const int cog = blockIdx.y;
    const int ntx = Wo >> 5;
    const int tileY = blockIdx.x / ntx;
    const int tileX = blockIdx.x - tileY * ntx;
    const int oh0 = tileY * 32, ow0 = tileX * 32;
    const int t = threadIdx.x;
    const int tx = t & 15, ty = t >> 4;

    float acc[8][4];
    #pragma unroll
    for (int i = 0; i < 8; i++)
        #pragma unroll
        for (int j = 0; j < 4; j++) acc[i][j] = 0.0f;

    const float* inb = in + (size_t)n * Ci * Hi * Wi;

    for (int cb = 0; cb < Ci; cb += 4) {
        __syncthreads();
        for (int i = t; i < 4 * 66 * 66; i += 256) {
            const int ci = i / 4356;
            const int rem = i - ci * 4356;
            const int r = rem / 66;
            const int c = rem - r * 66;
            const int ih = oh0 * 2 - 1 + r;
            const int iw = ow0 * 2 - 1 + c;
            const int cig = cb + ci;
            float v = 0.0f;
            if (cig < Ci && ih >= 0 && ih < Hi && iw >= 0 && iw < Wi)
                v = inb[(size_t)cig * Hi * Wi + ih * Wi + iw];
            sIn[ci][r][c] = v;
        }
        for (int i = t; i < 8 * 4 * 16; i += 256) {
            const int co = i >> 6;
            const int rem = i & 63;
            const int ci = rem >> 4;
            const int k = rem & 15;
            const int cig = cb + ci;
            sWp[i] = (cig < Ci)
                ? w[(((size_t)(cog * 8 + co)) * Ci + cig) * 16 + k] : 0.0f;
        }
        __syncthreads();

        #pragma unroll 1
        for (int ci = 0; ci < 4; ci++) {
            float iv[6][6];
            #pragma unroll
            for (int r = 0; r < 6; r++) {
                const float* rb = &sIn[ci][4 * ty + r][4 * tx];
                const float4 a = *reinterpret_cast<const float4*>(rb);
                const float2 b = *reinterpret_cast<const float2*>(rb + 4);
                iv[r][0] = a.x; iv[r][1] = a.y; iv[r][2] = a.z; iv[r][3] = a.w;
                iv[r][4] = b.x; iv[r][5] = b.y;
            }
            #pragma unroll
            for (int co = 0; co < 8; co++) {
                const float4* wq = reinterpret_cast<const float4*>(
                    sWp + (co * 4 + ci) * 16);
                const float4 q0 = wq[0], q1 = wq[1], q2 = wq[2], q3 = wq[3];
                float wv[16] = {q0.x, q0.y, q0.z, q0.w, q1.x, q1.y, q1.z, q1.w,
                                q2.x, q2.y, q2.z, q2.w, q3.x, q3.y, q3.z, q3.w};
                #pragma unroll
                for (int r2 = 0; r2 < 2; r2++)
                    #pragma unroll
                    for (int c2 = 0; c2 < 2; c2++) {
                        float a = acc[co][r2 * 2 + c2];
                        #pragma unroll
                        for (int kh = 0; kh < 4; kh++)
                            #pragma unroll
                            for (int kw = 0; kw < 4; kw++)
                                a = fmaf(iv[2 * r2 + kh][2 * c2 + kw],
                                         wv[kh * 4 + kw], a);
                        acc[co][r2 * 2 + c2] = a;
                    }
            }
        }
    }

    #pragma unroll
    for (int co = 0; co < 8; co++) {
        const float b = bias[cog * 8 + co];
        float* ob = out + ((size_t)n * Co + cog * 8 + co) * Ho * Wo;
        #pragma unroll
        for (int r2 = 0; r2 < 2; r2++) {
            const int oh = oh0 + 2 * ty + r2;
            *reinterpret_cast<float2*>(ob + (size_t)oh * Wo + ow0 + 2 * tx) =
                make_float2(acc[co][r2 * 2 + 0] + b, acc[co][r2 * 2 + 1] + b);
        }
    }
}

// ---------------------------------------------------------------------------
// 1x1 conv (round-3 version).
// ---------------------------------------------------------------------------
template <bool RELU, bool BIAS, bool RES>
__global__ void __launch_bounds__(256) conv1x1_k(
    const float* __restrict__ in, const float* __restrict__ w,
    const float* __restrict__ bias, const float* __restrict__ res,
    float* __restrict__ out, int Ci, int Co)
{
    __shared__ float sW1[8 * 128];
    const int n = blockIdx.z;
    const int cog = blockIdx.y;
    const int hw = blockIdx.x * 1024 + threadIdx.x * 4;
    const int t = threadIdx.x;

    for (int i = t; i < 8 * Ci; i += 256)
        sW1[i] = w[(size_t)cog * 8 * Ci + i];
    __syncthreads();

    const float* ip = in + (size_t)n * Ci * 4096 + hw;
    float4 acc[8];
    #pragma unroll
    for (int co = 0; co < 8; co++) acc[co] = make_float4(0.f, 0.f, 0.f, 0.f);

    #pragma unroll 2
    for (int ci = 0; ci < Ci; ci++) {
        const float4 xv = *reinterpret_cast<const float4*>(ip + (size_t)ci * 4096);
        #pragma unroll
        for (int co = 0; co < 8; co++) {
            const float wv = sW1[co * Ci + ci];
            acc[co].x = fmaf(xv.x, wv, acc[co].x);
            acc[co].y = fmaf(xv.y, wv, acc[co].y);
            acc[co].z = fmaf(xv.z, wv, acc[co].z);
            acc[co].w = fmaf(xv.w, wv, acc[co].w);
        }
    }

    #pragma unroll
    for (int co = 0; co < 8; co++) {
        float4 v = acc[co];
        if (BIAS) {
            const float b = bias[cog * 8 + co];
            v.x += b; v.y += b; v.z += b; v.w += b;
        }
        if (RELU) {
            v.x = fmaxf(v.x, 0.f); v.y = fmaxf(v.y, 0.f);
            v.z = fmaxf(v.z, 0.f); v.w = fmaxf(v.w, 0.f);
        }
        const size_t o = ((size_t)n * Co + cog * 8 + co) * 4096 + hw;
        if (RES) {
            const float4 r = *reinterpret_cast<const float4*>(res + o);
            v.x += r.x; v.y += r.y; v.z += r.z; v.w += r.w;
        }
        *reinterpret_cast<float4*>(out + o) = v;
    }
}

// ---------------------------------------------------------------------------
// Transposed conv k4 s2 p1 (round-3 version).
// ---------------------------------------------------------------------------
template <int CO_T>
__global__ void __launch_bounds__(256) deconv4x4s2_tiled(
    const float* __restrict__ in, const float* __restrict__ w,
    const float* __restrict__ bias, float* __restrict__ out,
    int Ci, int Hi, int Wi, int Co)
{
    __shared__ float sIn[8][18][36];
    __shared__ float sW[8 * CO_T * 16];

    const int n = blockIdx.z;
    const int cog = blockIdx.y;
    const int ntx = Wi >> 5;
    const int tileY = blockIdx.x / ntx;
    const int tileX = blockIdx.x - tileY * ntx;
    const int i0 = tileY * 16, j0 = tileX * 32;
    const int t = threadIdx.x;
    const int tx = t & 15, ty = t >> 4;

    float acc[CO_T][2][4];
    #pragma unroll
    for (int c = 0; c < CO_T; c++)
        #pragma unroll
        for (int a = 0; a < 2; a++)
            #pragma unroll
            for (int j = 0; j < 4; j++) acc[c][a][j] = 0.0f;

    const float* inb = in + (size_t)n * Ci * Hi * Wi;

    const int RR[2][2] = {{1, 0}, {2, 1}};
    const int KH[2][2] = {{1, 3}, {0, 2}};
    const int CC[2][2] = {{1, 0}, {2, 1}};
    const int KW[2][2] = {{1, 3}, {0, 2}};

    for (int cb = 0; cb < Ci; cb += 8) {
        __syncthreads();
        for (int i = t; i < 8 * 18 * 34; i += 256) {
            const int ci = i / 612;
            const int rem = i - ci * 612;
            const int r = rem / 34;
            const int c = rem - r * 34;
            const int ih = i0 - 1 + r;
            const int iw = j0 - 1 + c;
            float v = 0.0f;
            if (ih >= 0 && ih < Hi && iw >= 0 && iw < Wi)
                v = inb[(size_t)(cb + ci) * Hi * Wi + ih * Wi + iw];
            sIn[ci][r][c] = v;
        }
        for (int i = t; i < 8 * CO_T * 16; i += 256) {
            const int ci = i / (CO_T * 16);
            const int rem = i - ci * (CO_T * 16);
            const int co = rem >> 4;
            const int k = rem & 15;
            sW[i] = w[(((size_t)(cb + ci)) * Co + cog * CO_T + co) * 16 + k];
        }
        __syncthreads();

        #pragma unroll 1
        for (int ci = 0; ci < 8; ci++) {
            float iv[3][4];
            #pragma unroll
            for (int r = 0; r < 3; r++) {
                const float2* rp = reinterpret_cast<const float2*>(
                    &sIn[ci][ty + r][2 * tx]);
                const float2 a = rp[0], b = rp[1];
                iv[r][0] = a.x; iv[r][1] = a.y; iv[r][2] = b.x; iv[r][3] = b.y;
            }
            #pragma unroll
            for (int co = 0; co < CO_T; co++) {
                const float4* wq = reinterpret_cast<const float4*>(
                    sW + (ci * CO_T + co) * 16);
                const float4 q0 = wq[0], q1 = wq[1], q2 = wq[2], q3 = wq[3];
                float wv[16] = {q0.x, q0.y, q0.z, q0.w, q1.x, q1.y, q1.z, q1.w,
                                q2.x, q2.y, q2.z, q2.w, q3.x, q3.y, q3.z, q3.w};
                #pragma unroll
                for (int q = 0; q < 2; q++)
                    #pragma unroll
                    for (int a = 0; a < 2; a++)
                        #pragma unroll
                        for (int b = 0; b < 2; b++) {
                            float s = acc[co][a][2 * q + b];
                            #pragma unroll
                            for (int si = 0; si < 2; si++)
                                #pragma unroll
                                for (int ti = 0; ti < 2; ti++)
                                    s = fmaf(iv[RR[a][si]][q + CC[b][ti]],
                                             wv[KH[a][si] * 4 + KW[b][ti]], s);
                            acc[co][a][2 * q + b] = s;
                        }
            }
        }
    }

    const int Ho = 2 * Hi, Wo = 2 * Wi;
    const int ow = 2 * j0 + 4 * tx;
    #pragma unroll
    for (int co = 0; co < CO_T; co++) {
        const float b = bias[cog * CO_T + co];
        float* ob = out + ((size_t)n * Co + cog * CO_T + co) * Ho * Wo;
        #pragma unroll
        for (int a = 0; a < 2; a++) {
            const int oh = 2 * (i0 + ty) + a;
            *reinterpret_cast<float4*>(ob + (size_t)oh * Wo + ow) =
                make_float4(acc[co][a][0] + b, acc[co][a][1] + b,
                            acc[co][a][2] + b, acc[co][a][3] + b);
        }
    }
}

// ---------------------------------------------------------------------------
__device__ __forceinline__ float blockReduceSum(float v) {
    __shared__ float sh[32];
    #pragma unroll
    for (int o = 16; o > 0; o >>= 1) v += __shfl_down_sync(0xffffffffu, v, o);
    if ((threadIdx.x & 31) == 0) sh[threadIdx.x >> 5] = v;
    __syncthreads();
    const int nw = (blockDim.x + 31) >> 5;
    v = (threadIdx.x < (unsigned)nw) ? sh[threadIdx.x] : 0.0f;
    if (threadIdx.x < 32) {
        #pragma unroll
        for (int o = 16; o > 0; o >>= 1) v += __shfl_down_sync(0xffffffffu, v, o);
    }
    return v;
}

#define VQ_K 512
#define VQ_D 64
#define VQ_SMEM ((VQ_K * VQ_D + VQ_K) * 4)

__global__ void __launch_bounds__(256) vq_kernel(
    const float* __restrict__ z, const float* __restrict__ cb,
    float* __restrict__ q)
{
    extern __shared__ float smem[];
    float* scb = smem;
    float* snorm = smem + VQ_K * VQ_D;

    for (int i = threadIdx.x; i < VQ_K * VQ_D; i += blockDim.x)
        scb[i] = cb[i];
    __syncthreads();
    for (int c = threadIdx.x; c < VQ_K; c += blockDim.x) {
        float s = 0.0f;
        const float* cp = scb + c * VQ_D;
        #pragma unroll 16
        for (int d = 0; d < VQ_D; d++) s = fmaf(cp[d], cp[d], s);
        snorm[c] = s;
    }
    __syncthreads();

    const int pos = blockIdx.x * blockDim.x + threadIdx.x;
    const int n = pos >> 12;
    const int hw = pos & 4095;

    float zv[VQ_D];
    const float* zp = z + (size_t)n * VQ_D * 4096 + hw;
    float zn = 0.0f;
    #pragma unroll
    for (int d = 0; d < VQ_D; d++) {
        zv[d] = zp[(size_t)d * 4096];
        zn = fmaf(zv[d], zv[d], zn);
    }

    float bestd = 3.402823466e+38f;
    int besti = 0;
    for (int c = 0; c < VQ_K; c++) {
        const float4* cp4 = reinterpret_cast<const float4*>(scb + c * VQ_D);
        float dot = 0.0f;
        #pragma unroll
        for (int d4 = 0; d4 < VQ_D / 4; d4++) {
            const float4 cv = cp4[d4];
            dot = fmaf(zv[4 * d4 + 0], cv.x, dot);
            dot = fmaf(zv[4 * d4 + 1], cv.y, dot);
            dot = fmaf(zv[4 * d4 + 2], cv.z, dot);
            dot = fmaf(zv[4 * d4 + 3], cv.w, dot);
        }
        const float dist = zn - 2.0f * dot + snorm[c];
        if (dist < bestd) { bestd = dist; besti = c; }
    }

    float lsum = 0.0f;
    const float* cp = scb + besti * VQ_D;
    float* qp = q + (size_t)n * VQ_D * 4096 + hw;
    #pragma unroll
    for (int d = 0; d < VQ_D; d++) {
        const float cv = cp[d];
        qp[(size_t)d * 4096] = cv;
        const float df = zv[d] - cv;
        lsum = fmaf(df, df, lsum);
    }
    const float bsum = blockReduceSum(lsum);
    if (threadIdx.x == 0) atomicAdd(&g_vq_loss, (double)bsum);
}

__global__ void __launch_bounds__(256) recon_loss_kernel(
    const float* __restrict__ rec, const float* __restrict__ inp, int total)
{
    float lsum = 0.0f;
    for (int i = blockIdx.x * blockDim.x + threadIdx.x; i < total;
         i += gridDim.x * blockDim.x) {
        const float d = rec[i] - inp[i];
        lsum = fmaf(d, d, lsum);
    }
    const float bsum = blockReduceSum(lsum);
    if (threadIdx.x == 0) atomicAdd(&g_rec_loss, (double)bsum);
}

__global__ void finalize_kernel(float* out, int out_size) {
    const double recon = g_rec_loss / 3145728.0;
    const double vq = g_vq_loss / 4194304.0;
    out[out_size - 2] = (float)(recon + 1.25 * vq);
    out[out_size - 1] = (float)recon;
}

// ---------------------------------------------------------------------------
extern "C" void kernel_launch(void* const* d_in, const int* in_sizes, int n_in,
                              void* d_out, int out_size)
{
    const float* inp        = (const float*)d_in[0];
    const float* enc_w1     = (const float*)d_in[1];
    const float* enc_b1     = (const float*)d_in[2];
    const float* enc_w2     = (const float*)d_in[3];
    const float* enc_b2     = (const float*)d_in[4];
    const float* enc_w3     = (const float*)d_in[5];
    const float* enc_b3     = (const float*)d_in[6];
    const float* enc_res_w1 = (const float*)d_in[7];
    const float* enc_res_w2 = (const float*)d_in[8];
    const float* vq_w       = (const float*)d_in[9];
    const float* vq_b       = (const float*)d_in[10];
    const float* codebook   = (const float*)d_in[11];
    const float* dec_w1     = (const float*)d_in[12];
    const float* dec_b1     = (const float*)d_in[13];
    const float* dec_res_w1 = (const float*)d_in[14];
    const float* dec_res_w2 = (const float*)d_in[15];
    const float* dec_w2t    = (const float*)d_in[16];
    const float* dec_b2     = (const float*)d_in[17];
    const float* dec_w3t    = (const float*)d_in[18];
    const float* dec_b3     = (const float*)d_in[19];

    float *bufA, *bufB, *bufC, *half, *zb, *qb, *d1, *d2, *eb;
    cudaGetSymbolAddress((void**)&bufA, g_bufA);
    cudaGetSymbolAddress((void**)&bufB, g_bufB);
    cudaGetSymbolAddress((void**)&bufC, g_bufC);
    cudaGetSymbolAddress((void**)&half, g_half);
    cudaGetSymbolAddress((void**)&zb, g_z);
    cudaGetSymbolAddress((void**)&qb, g_q);
    cudaGetSymbolAddress((void**)&d1, g_d1);
    cudaGetSymbolAddress((void**)&d2, g_d2);
    cudaGetSymbolAddress((void**)&eb, g_e);

    cudaFuncSetAttribute(vq_kernel, cudaFuncAttributeMaxDynamicSharedMemorySize,
                         VQ_SMEM);
    cudaFuncSetAttribute(conv4x4s2_tiled,
                         cudaFuncAttributeMaxDynamicSharedMemorySize, K4_SMEM);
    cudaFuncSetAttribute(conv3x3_big<false, true>,
                         cudaFuncAttributeMaxDynamicSharedMemorySize, C3_SMEM);
    cudaFuncSetAttribute(conv3x3_big<true, false>,
                         cudaFuncAttributeMaxDynamicSharedMemorySize, C3_SMEM);

    zero_losses_kernel<<<1, 1>>>();

    // ---- Encoder ----
    conv4x4s2_tiled<<<dim3(16, 8, NB), 256, K4_SMEM>>>(
        inp, enc_w1, enc_b1, bufA, 3, 256, 256, 64, 128, 128);
    conv4x4s2_tiled<<<dim3(4, 16, NB), 256, K4_SMEM>>>(
        bufA, enc_w2, enc_b2, bufB, 64, 128, 128, 128, 64, 64);
    conv3x3_big<false, true><<<dim3(2, 16, NB), 256, C3_SMEM>>>(
        bufB, enc_w3, enc_b3, bufC, 128, 128);

    {
        float* cur = bufC;
        float* alt = bufB;
        for (int i = 0; i < 3; i++) {
            conv3x3_big<true, false><<<dim3(2, 8, NB), 256, C3_SMEM>>>(
                cur, enc_res_w1 + (size_t)i * 64 * 128 * 9, nullptr, half,
                128, 64);
            conv1x1_k<true, false, true><<<dim3(4, 16, NB), 256>>>(
                half, enc_res_w2 + (size_t)i * 128 * 64, nullptr, cur, alt,
                64, 128);
            float* t = cur; cur = alt; alt = t;
        }
        conv1x1_k<false, true, false><<<dim3(4, 8, NB), 256>>>(
            cur, vq_w, vq_b, nullptr, zb, 128, 64);
    }

    // ---- VQ ----
    vq_kernel<<<256, 256, VQ_SMEM>>>(zb, codebook, qb);

    // ---- Decoder ----
    conv3x3_big<false, true><<<dim3(2, 8, NB), 256, C3_SMEM>>>(
        qb, dec_w1, dec_b1, d1, 64, 64);
    {
        float* cur = d1;
        float* alt = d2;
        for (int i = 0; i < 3; i++) {
            conv3x3_big<true, false><<<dim3(2, 4, NB), 256, C3_SMEM>>>(
                cur, dec_res_w1 + (size_t)i * 32 * 64 * 9, nullptr, half,
                64, 32);
            conv1x1_k<true, false, true><<<dim3(4, 8, NB), 256>>>(
                half, dec_res_w2 + (size_t)i * 64 * 32, nullptr, cur, alt,
                32, 64);
            float* t = cur; cur = alt; alt = t;
        }
        deconv4x4s2_tiled<4><<<dim3(8, 8, NB), 256>>>(
            cur, dec_w2t, dec_b2, eb, 64, 64, 64, 32);
    }
    deconv4x4s2_tiled<3><<<dim3(32, 1, NB), 256>>>(
        eb, dec_w3t, dec_b3, (float*)d_out, 32, 128, 128, 3);

    // ---- Losses ----
    recon_loss_kernel<<<1024, 256>>>((const float*)d_out, inp, 3145728);
    finalize_kernel<<<1, 1>>>((float*)d_out, out_size);
}